// round 15
// baseline (speedup 1.0000x reference)
#include <cuda_runtime.h>
#include <math.h>

#define N_PART   16384
#define DDIM     16
#define PDIM     8
#define M_STEPS  50
#define HDIM     128
#define PPC      111       // particles per CTA (148 CTAs cover 16384)
#define BLK_R    112       // padded row count = 7 row-groups of 16
#define NROW     7         // row-groups per thread tile
#define NTHREADS 256
#define LDIN     16        // sIn row stride (X only)
#define LDH      132       // sH / base row stride (132 mod 32 = 4 -> conflict-free)

typedef unsigned long long u64;

static __device__ __forceinline__ u64 pack2(float x, float y) {
    u64 r;
    asm("mov.b64 %0, {%1, %2};" : "=l"(r) : "f"(x), "f"(y));
    return r;
}
static __device__ __forceinline__ u64 fma2(u64 a, u64 b, u64 c) {
    u64 d;
    asm("fma.rn.f32x2 %0, %1, %2, %3;" : "=l"(d) : "l"(a), "l"(b), "l"(c));
    return d;
}
static __device__ __forceinline__ float2 unpack2(u64 v) {
    float2 f;
    asm("mov.b64 {%0, %1}, %2;" : "=f"(f.x), "=f"(f.y) : "l"(v));
    return f;
}

// C tile: NROW rows (ty + 16*i) x 8 cols ({4tx..4tx+3} U {64+4tx..64+4tx+3}).
// A rows at stride 16*LDA, k-chunks of 4 read as float4.
// B: per k, two float4 at [k*LDB+4tx] and [k*LDB+64+4tx]; prefetch 1 k ahead.
// Over-reads one B row / one A chunk past the end (stays inside smem).
template <int K4, int LDA, int LDB>
static __device__ __forceinline__ void mm_tile_v(const float* __restrict__ A,
                                                 const float* __restrict__ B,
                                                 u64 c[NROW][4]) {
    float4 a[NROW];
#pragma unroll
    for (int i = 0; i < NROW; i++)
        a[i] = *(const float4*)(A + i * 16 * LDA);
    float4 bA = *(const float4*)(B);
    float4 bB = *(const float4*)(B + 64);

#pragma unroll 2
    for (int kk = 0; kk < K4; kk++) {
#pragma unroll
        for (int j = 0; j < 4; j++) {
            const int k = 4 * kk + j;
            float4 nA = *(const float4*)(B + (size_t)(k + 1) * LDB);
            float4 nB = *(const float4*)(B + (size_t)(k + 1) * LDB + 64);
            float4 an[NROW];
            if (j == 3) {
#pragma unroll
                for (int i = 0; i < NROW; i++)
                    an[i] = *(const float4*)(A + i * 16 * LDA + 4 * (kk + 1));
            }
            const u64* bAp = (const u64*)&bA;
            const u64* bBp = (const u64*)&bB;
            u64 b0 = bAp[0], b1 = bAp[1], b2 = bBp[0], b3 = bBp[1];
#pragma unroll
            for (int i = 0; i < NROW; i++) {
                const float* af = (const float*)&a[i];
                float av = af[j];
                u64 a2 = pack2(av, av);
                c[i][0] = fma2(a2, b0, c[i][0]);
                c[i][1] = fma2(a2, b1, c[i][1]);
                c[i][2] = fma2(a2, b2, c[i][2]);
                c[i][3] = fma2(a2, b3, c[i][3]);
            }
            bA = nA; bB = nB;
            if (j == 3) {
#pragma unroll
                for (int i = 0; i < NROW; i++) a[i] = an[i];
            }
        }
    }
}

static __device__ __forceinline__ void store_relu_bias(float* __restrict__ dst,
                                                       int ty, int tx,
                                                       const u64 c[NROW][4],
                                                       float4 biasA, float4 biasB) {
#pragma unroll
    for (int i = 0; i < NROW; i++) {
        float* drow = dst + (ty + 16 * i) * LDH;
        float2 v0 = unpack2(c[i][0]);
        float2 v1 = unpack2(c[i][1]);
        float4 o;
        o.x = fmaxf(v0.x + biasA.x, 0.0f);
        o.y = fmaxf(v0.y + biasA.y, 0.0f);
        o.z = fmaxf(v1.x + biasA.z, 0.0f);
        o.w = fmaxf(v1.y + biasA.w, 0.0f);
        *(float4*)(drow + 4 * tx) = o;
        float2 w0 = unpack2(c[i][2]);
        float2 w1 = unpack2(c[i][3]);
        float4 q;
        q.x = fmaxf(w0.x + biasB.x, 0.0f);
        q.y = fmaxf(w0.y + biasB.y, 0.0f);
        q.z = fmaxf(w1.x + biasB.z, 0.0f);
        q.w = fmaxf(w1.y + biasB.w, 0.0f);
        *(float4*)(drow + 64 + 4 * tx) = q;
    }
}

static __device__ __forceinline__ void store_relu(float* __restrict__ dst,
                                                  int ty, int tx,
                                                  const u64 c[NROW][4]) {
#pragma unroll
    for (int i = 0; i < NROW; i++) {
        float* drow = dst + (ty + 16 * i) * LDH;
        float2 v0 = unpack2(c[i][0]);
        float2 v1 = unpack2(c[i][1]);
        float4 o;
        o.x = fmaxf(v0.x, 0.0f); o.y = fmaxf(v0.y, 0.0f);
        o.z = fmaxf(v1.x, 0.0f); o.w = fmaxf(v1.y, 0.0f);
        *(float4*)(drow + 4 * tx) = o;
        float2 w0 = unpack2(c[i][2]);
        float2 w1 = unpack2(c[i][3]);
        float4 q;
        q.x = fmaxf(w0.x, 0.0f); q.y = fmaxf(w0.y, 0.0f);
        q.z = fmaxf(w1.x, 0.0f); q.w = fmaxf(w1.y, 0.0f);
        *(float4*)(drow + 64 + 4 * tx) = q;
    }
}

__global__ void __launch_bounds__(NTHREADS, 1)
sde_rollout_kernel(const float* __restrict__ X0, const float* __restrict__ V0,
                   const float* __restrict__ obs, const float* __restrict__ noise,
                   const float* __restrict__ W1, const float* __restrict__ b1,
                   const float* __restrict__ W2, const float* __restrict__ b2,
                   const float* __restrict__ W3, const float* __restrict__ b3,
                   float* __restrict__ out) {
    extern __shared__ float sm[];
    float* W1xs = sm;                       // 16*128 = 2048  (W1 rows 1..16: X part)
    float* w1ts = W1xs + 16 * HDIM;         // 128            (W1 row 0: t part)
    float* b1s  = w1ts + HDIM;              // 128
    float* W2s  = b1s + HDIM;               // 128*128 = 16384
    float* b2s  = W2s + HDIM * HDIM;        // 128
    float* W3s  = b2s + HDIM;               // 128*16 = 2048
    float* b3s  = W3s + HDIM * DDIM;        // 16
    float* sIn  = b3s + 16;                 // 128*16 = 2048  (X state, rows 0..111 used)
    float* sH   = sIn + 128 * LDIN;         // 128*132 = 16896
    float* sV   = sH + 128 * LDH;           // 128
    float* base = sV + 128;                 // 128*132 = 16896 (obs@W1o + b1)
    // total = 56848 floats = 227392 B

    const int tid = threadIdx.x;
    const int pbase = blockIdx.x * PPC;
    const int count = min(PPC, N_PART - pbase);     // real particles in this CTA

    // ---- cooperative weight load ----
    for (int i = tid; i < (16 * HDIM) / 4; i += NTHREADS)
        ((float4*)W1xs)[i] = ((const float4*)(W1 + HDIM))[i];       // rows 1..16
    for (int i = tid; i < (HDIM * HDIM) / 4; i += NTHREADS)
        ((float4*)W2s)[i] = ((const float4*)W2)[i];
    for (int i = tid; i < (HDIM * DDIM) / 4; i += NTHREADS)
        ((float4*)W3s)[i] = ((const float4*)W3)[i];
    if (tid < HDIM) {
        w1ts[tid] = W1[tid];                                        // row 0
        b1s[tid] = b1[tid];
        b2s[tid] = b2[tid];
    }
    if (tid < DDIM) b3s[tid] = b3[tid];
    // W1 obs rows (17..24) -> scratch: base rows 0..7
    for (int s = tid; s < PDIM * HDIM; s += NTHREADS) {
        int k = s >> 7, cc = s & 127;
        base[k * LDH + cc] = W1[(17 + k) * HDIM + cc];
    }

    // ---- init particle state (2 threads per particle, 8 dims each) ----
    const int p  = tid >> 1;            // 0..127 (rows >= BLK_R unused)
    const int dh = (tid & 1) * 8;
    const int pg = pbase + p;
    const int pgc = pg < N_PART ? pg : N_PART - 1;   // clamped for loads
    if (p < BLK_R) {
        float4 xa, xb;
        if (p < count) {
            xa = *(const float4*)(X0 + (size_t)pg * DDIM + dh);
            xb = *(const float4*)(X0 + (size_t)pg * DDIM + dh + 4);
        } else {
            xa = make_float4(0.f, 0.f, 0.f, 0.f);
            xb = xa;
        }
        *(float4*)(sIn + p * LDIN + dh)     = xa;
        *(float4*)(sIn + p * LDIN + dh + 4) = xb;
        if ((tid & 1) == 0) {
            sV[p] = (p < count) ? V0[pg] : 0.0f;
#pragma unroll
            for (int j = 0; j < PDIM; j++)
                sH[p * LDH + j] = (p < count) ? obs[(size_t)pg * PDIM + j] : 0.0f;
        }
    }
    __syncthreads();

    const int ty = tid >> 4, tx = tid & 15;

    // ---- base = obs @ W1o + b1 (one-time K=8 GEMM) ----
    {
        float acc[NROW][8];
#pragma unroll
        for (int i = 0; i < NROW; i++)
#pragma unroll
            for (int j = 0; j < 8; j++) acc[i][j] = 0.0f;
        for (int k = 0; k < PDIM; k++) {
            float w[8];
#pragma unroll
            for (int j = 0; j < 4; j++) {
                w[j]     = base[k * LDH + 4 * tx + j];
                w[4 + j] = base[k * LDH + 64 + 4 * tx + j];
            }
#pragma unroll
            for (int i = 0; i < NROW; i++) {
                float o = sH[(ty + 16 * i) * LDH + k];
#pragma unroll
                for (int j = 0; j < 8; j++)
                    acc[i][j] = fmaf(o, w[j], acc[i][j]);
            }
        }
        __syncthreads();    // all W1o reads done before base is overwritten
        float4 c0 = *(const float4*)(b1s + 4 * tx);
        float4 c1 = *(const float4*)(b1s + 64 + 4 * tx);
#pragma unroll
        for (int i = 0; i < NROW; i++) {
            int row = ty + 16 * i;
            float4 o0 = { acc[i][0] + c0.x, acc[i][1] + c0.y,
                          acc[i][2] + c0.z, acc[i][3] + c0.w };
            float4 o1 = { acc[i][4] + c1.x, acc[i][5] + c1.y,
                          acc[i][6] + c1.z, acc[i][7] + c1.w };
            *(float4*)(base + row * LDH + 4 * tx) = o0;
            *(float4*)(base + row * LDH + 64 + 4 * tx) = o1;
        }
    }
    __syncthreads();

    const float dt   = (float)(1.0 / (double)M_STEPS);  // T = 1
    const float sqdt = sqrtf(dt);

    // loop-invariant fragments -> registers
    const float4 b2A = *(const float4*)(b2s + 4 * tx);
    const float4 b2B = *(const float4*)(b2s + 64 + 4 * tx);
    const float4 b3a = *(const float4*)(b3s + dh);
    const float4 b3b = *(const float4*)(b3s + dh + 4);
    const float4 w1A = *(const float4*)(w1ts + 4 * tx);
    const float4 w1B = *(const float4*)(w1ts + 64 + 4 * tx);

    for (int m = 0; m < M_STEPS; m++) {
        const float t = (float)m * dt;
        float tw[8] = { t * w1A.x, t * w1A.y, t * w1A.z, t * w1A.w,
                        t * w1B.x, t * w1B.y, t * w1B.z, t * w1B.w };

        // ---- layer 1: h1 = relu(X@W1x + t*W1t + base), K=16 ----
        u64 c[NROW][4];
#pragma unroll
        for (int i = 0; i < NROW; i++) {
            const float* brow = base + (ty + 16 * i) * LDH;
            float4 fA = *(const float4*)(brow + 4 * tx);
            float4 fB = *(const float4*)(brow + 64 + 4 * tx);
            c[i][0] = pack2(fA.x + tw[0], fA.y + tw[1]);
            c[i][1] = pack2(fA.z + tw[2], fA.w + tw[3]);
            c[i][2] = pack2(fB.x + tw[4], fB.y + tw[5]);
            c[i][3] = pack2(fB.z + tw[6], fB.w + tw[7]);
        }
        mm_tile_v<4, LDIN, HDIM>(sIn + ty * LDIN, W1xs + 4 * tx, c);
        store_relu(sH, ty, tx, c);
        __syncthreads();

        // ---- layer 2: h2 = relu(h1 @ W2 + b2) ----
#pragma unroll
        for (int i = 0; i < NROW; i++) { c[i][0]=0; c[i][1]=0; c[i][2]=0; c[i][3]=0; }
        mm_tile_v<HDIM / 4, LDH, HDIM>(sH + ty * LDH, W2s + 4 * tx, c);

        // prefetch this step's noise (hides behind syncs + layer 3)
        float4 e0, e1;
        if (p < BLK_R) {
            const float* np = noise + (((size_t)m * N_PART + pgc) * DDIM + dh);
            e0 = *(const float4*)np;
            e1 = *(const float4*)(np + 4);
        }

        __syncthreads();                            // everyone done reading h1
        store_relu_bias(sH, ty, tx, c, b2A, b2B);
        __syncthreads();

        if (p < BLK_R) {   // warps 0..6 only (tid < 224)
            // ---- layer 3: Z = h2 @ W3 + b3 (2 threads/particle, 8 dims each) ----
            u64 cz[4] = {0, 0, 0, 0};
            const float* hrow = sH + p * LDH;
#pragma unroll 4
            for (int kk = 0; kk < HDIM / 4; kk++) {
                float4 hv = *(const float4*)(hrow + 4 * kk);
                const float* hf = (const float*)&hv;
#pragma unroll
                for (int j = 0; j < 4; j++) {
                    const int k = 4 * kk + j;
                    u64 a2 = pack2(hf[j], hf[j]);
                    ulonglong2 w01 = *(const ulonglong2*)(W3s + k * DDIM + dh);
                    ulonglong2 w23 = *(const ulonglong2*)(W3s + k * DDIM + dh + 4);
                    cz[0] = fma2(a2, w01.x, cz[0]);
                    cz[1] = fma2(a2, w01.y, cz[1]);
                    cz[2] = fma2(a2, w23.x, cz[2]);
                    cz[3] = fma2(a2, w23.y, cz[3]);
                }
            }
            const float* b3f = (const float*)&b3a;
            const float* b3g = (const float*)&b3b;
            float z[8];
            {
                float2 v0 = unpack2(cz[0]), v1 = unpack2(cz[1]);
                float2 v2 = unpack2(cz[2]), v3 = unpack2(cz[3]);
                z[0] = v0.x + b3f[0]; z[1] = v0.y + b3f[1];
                z[2] = v1.x + b3f[2]; z[3] = v1.y + b3f[3];
                z[4] = v2.x + b3g[0]; z[5] = v2.y + b3g[1];
                z[6] = v3.x + b3g[2]; z[7] = v3.y + b3g[3];
            }
            float eps[8] = {e0.x, e0.y, e0.z, e0.w, e1.x, e1.y, e1.z, e1.w};

            float zz = 0.0f, zw = 0.0f;
#pragma unroll
            for (int j = 0; j < 8; j++) {
                zz = fmaf(z[j], z[j], zz);
                zw = fmaf(z[j], sqdt * eps[j], zw);
            }
            zz += __shfl_xor_sync(0xffffffffu, zz, 1);
            zw += __shfl_xor_sync(0xffffffffu, zw, 1);

            // X <- X*(1-dt) + sqrt(dt)*eps   (sigma = 1)
            float* xr = sIn + p * LDIN + dh;
            float4 xv0 = *(const float4*)xr;
            float4 xv1 = *(const float4*)(xr + 4);
            xv0.x = fmaf(xv0.x, 1.0f - dt, sqdt * eps[0]);
            xv0.y = fmaf(xv0.y, 1.0f - dt, sqdt * eps[1]);
            xv0.z = fmaf(xv0.z, 1.0f - dt, sqdt * eps[2]);
            xv0.w = fmaf(xv0.w, 1.0f - dt, sqdt * eps[3]);
            xv1.x = fmaf(xv1.x, 1.0f - dt, sqdt * eps[4]);
            xv1.y = fmaf(xv1.y, 1.0f - dt, sqdt * eps[5]);
            xv1.z = fmaf(xv1.z, 1.0f - dt, sqdt * eps[6]);
            xv1.w = fmaf(xv1.w, 1.0f - dt, sqdt * eps[7]);
            *(float4*)xr = xv0;
            *(float4*)(xr + 4) = xv1;

            if ((tid & 1) == 0)
                sV[p] = sV[p] + dt * 0.5f * zz + zw;     // V update
        }
        __syncthreads();
    }

    // ---- write outputs: X (N*16) then V (N), real particles only ----
    if (p < count) {
        float* xo = out + (size_t)pg * DDIM + dh;
        const float* xr = sIn + p * LDIN + dh;
        *(float4*)xo = *(const float4*)xr;
        *(float4*)(xo + 4) = *(const float4*)(xr + 4);
        if ((tid & 1) == 0) out[(size_t)N_PART * DDIM + pg] = sV[p];
    }
}

extern "C" void kernel_launch(void* const* d_in, const int* in_sizes, int n_in,
                              void* d_out, int out_size) {
    const float* X0    = (const float*)d_in[0];
    const float* V0    = (const float*)d_in[1];
    const float* obs   = (const float*)d_in[2];
    const float* noise = (const float*)d_in[3];
    const float* W1    = (const float*)d_in[4];
    const float* b1    = (const float*)d_in[5];
    const float* W2    = (const float*)d_in[6];
    const float* b2    = (const float*)d_in[7];
    const float* W3    = (const float*)d_in[8];
    const float* b3    = (const float*)d_in[9];
    float* out = (float*)d_out;

    const size_t smem_bytes = (size_t)56848 * sizeof(float);   // 227392 B

    cudaFuncSetAttribute(sde_rollout_kernel,
                         cudaFuncAttributeMaxDynamicSharedMemorySize,
                         (int)smem_bytes);

    const int grid = (N_PART + PPC - 1) / PPC;   // 148
    sde_rollout_kernel<<<grid, NTHREADS, smem_bytes>>>(
        X0, V0, obs, noise, W1, b1, W2, b2, W3, b3, out);
}

// round 17
// speedup vs baseline: 1.1667x; 1.1667x over previous
#include <cuda_runtime.h>
#include <math.h>
#include <stdint.h>

#define N_PART   16384
#define DDIM     16
#define PDIM     8
#define M_STEPS  50
#define HDIM     128
#define PPC      111
#define BLK_R    112
#define NROW     7
#define NTHREADS 256
#define LDIN     28        // sIn row = [t, X16, obs8, pad3]
#define LDK      136       // bf16 tile row stride (272B == 68 words == 4 mod 32)
#define LDZ      20        // zbuf row stride (f32)

typedef unsigned long long u64;

// ---------------- smem byte offsets (all 16B aligned) ----------------
#define SM_AHI   0         // h1 hi tile  128 x LDK bf16 = 34816B
#define SM_ALO   34816     // h1 lo tile
#define SM_BHI   69632     // W2^T hi  (Bt[n][k])
#define SM_BLO   104448    // W2^T lo
#define SM_W1    139264    // 29 x 128 f32 (rows 25..28 zero)   14848B
#define SM_B1    154112
#define SM_B2    154624
#define SM_B3    155136
#define SM_W3    155200    // 128 x 16 f32
#define SM_SIN   163392    // 128 x 28 f32
#define SM_SV    177728
#define SM_ZB    178240    // 2 x 128 x LDZ f32 = 20480B
#define SM_TOTAL 198720

static __device__ __forceinline__ u64 pack2(float x, float y) {
    u64 r; asm("mov.b64 %0, {%1, %2};" : "=l"(r) : "f"(x), "f"(y)); return r;
}
static __device__ __forceinline__ u64 fma2(u64 a, u64 b, u64 c) {
    u64 d; asm("fma.rn.f32x2 %0, %1, %2, %3;" : "=l"(d) : "l"(a), "l"(b), "l"(c)); return d;
}
static __device__ __forceinline__ float2 unpack2(u64 v) {
    float2 f; asm("mov.b64 {%0, %1}, %2;" : "=f"(f.x), "=f"(f.y) : "l"(v)); return f;
}
static __device__ __forceinline__ uint32_t bf16_hi_bits(float x) {
    uint32_t u = __float_as_uint(x);
    return (u + 0x7FFFu + ((u >> 16) & 1u)) & 0xFFFF0000u;
}
static __device__ __forceinline__ uint32_t bf16x2_rn(float lo, float hi) {
    uint32_t r; asm("cvt.rn.bf16x2.f32 %0, %1, %2;" : "=r"(r) : "f"(hi), "f"(lo)); return r;
}
static __device__ __forceinline__ void ldsm4(uint32_t r[4], uint32_t addr) {
    asm volatile("ldmatrix.sync.aligned.m8n8.x4.shared.b16 {%0,%1,%2,%3}, [%4];"
        : "=r"(r[0]), "=r"(r[1]), "=r"(r[2]), "=r"(r[3]) : "r"(addr));
}
static __device__ __forceinline__ void mma_bf16(float d[4], const uint32_t a[4],
                                                uint32_t b0, uint32_t b1) {
    asm volatile("mma.sync.aligned.m16n8k16.row.col.f32.bf16.bf16.f32 "
        "{%0,%1,%2,%3}, {%4,%5,%6,%7}, {%8,%9}, {%0,%1,%2,%3};"
        : "+f"(d[0]), "+f"(d[1]), "+f"(d[2]), "+f"(d[3])
        : "r"(a[0]), "r"(a[1]), "r"(a[2]), "r"(a[3]), "r"(b0), "r"(b1));
}
static __device__ __forceinline__ uint32_t smem_u32(const void* p) {
    uint32_t a;
    asm("{ .reg .u64 t; cvta.to.shared.u64 t, %1; cvt.u32.u64 %0, t; }" : "=r"(a) : "l"(p));
    return a;
}

static __device__ __forceinline__ void split_store4(char* smem, uint32_t off,
                                                    float v0, float v1, float v2, float v3) {
    uint32_t h0 = bf16_hi_bits(v0), h1 = bf16_hi_bits(v1);
    uint32_t h2 = bf16_hi_bits(v2), h3 = bf16_hi_bits(v3);
    uint32_t hiA = __byte_perm(h0, h1, 0x7632);
    uint32_t hiB = __byte_perm(h2, h3, 0x7632);
    *(u64*)(smem + SM_AHI + off) = (u64)hiA | ((u64)hiB << 32);
    float l0 = v0 - __uint_as_float(h0), l1 = v1 - __uint_as_float(h1);
    float l2 = v2 - __uint_as_float(h2), l3 = v3 - __uint_as_float(h3);
    uint32_t loA = bf16x2_rn(l0, l1), loB = bf16x2_rn(l2, l3);
    *(u64*)(smem + SM_ALO + off) = (u64)loA | ((u64)loB << 32);
}

template <int K4, int LDA, int LDB>
static __device__ __forceinline__ void mm_tile_v(const float* __restrict__ A,
                                                 const float* __restrict__ B,
                                                 u64 c[NROW][4]) {
    float4 a[NROW];
#pragma unroll
    for (int i = 0; i < NROW; i++)
        a[i] = *(const float4*)(A + i * 16 * LDA);
    float4 bA = *(const float4*)(B);
    float4 bB = *(const float4*)(B + 64);
#pragma unroll 2
    for (int kk = 0; kk < K4; kk++) {
#pragma unroll
        for (int j = 0; j < 4; j++) {
            const int k = 4 * kk + j;
            float4 nA = *(const float4*)(B + (size_t)(k + 1) * LDB);
            float4 nB = *(const float4*)(B + (size_t)(k + 1) * LDB + 64);
            float4 an[NROW];
            if (j == 3) {
#pragma unroll
                for (int i = 0; i < NROW; i++)
                    an[i] = *(const float4*)(A + i * 16 * LDA + 4 * (kk + 1));
            }
            const u64* bAp = (const u64*)&bA;
            const u64* bBp = (const u64*)&bB;
            u64 b0 = bAp[0], b1 = bAp[1], b2 = bBp[0], b3 = bBp[1];
#pragma unroll
            for (int i = 0; i < NROW; i++) {
                const float* af = (const float*)&a[i];
                float av = af[j];
                u64 a2 = pack2(av, av);
                c[i][0] = fma2(a2, b0, c[i][0]);
                c[i][1] = fma2(a2, b1, c[i][1]);
                c[i][2] = fma2(a2, b2, c[i][2]);
                c[i][3] = fma2(a2, b3, c[i][3]);
            }
            bA = nA; bB = nB;
            if (j == 3) {
#pragma unroll
                for (int i = 0; i < NROW; i++) a[i] = an[i];
            }
        }
    }
}

__global__ void __launch_bounds__(NTHREADS, 1)
sde_rollout_kernel(const float* __restrict__ X0, const float* __restrict__ V0,
                   const float* __restrict__ obs, const float* __restrict__ noise,
                   const float* __restrict__ W1, const float* __restrict__ b1,
                   const float* __restrict__ W2, const float* __restrict__ b2,
                   const float* __restrict__ W3, const float* __restrict__ b3,
                   float* __restrict__ out) {
    extern __shared__ char smem[];
    const uint32_t sb = smem_u32(smem);
    float* W1s  = (float*)(smem + SM_W1);
    float* b1s  = (float*)(smem + SM_B1);
    float* b2s  = (float*)(smem + SM_B2);
    float* b3s  = (float*)(smem + SM_B3);
    float* W3s  = (float*)(smem + SM_W3);
    float* sIn  = (float*)(smem + SM_SIN);
    float* sV   = (float*)(smem + SM_SV);
    float* zbuf = (float*)(smem + SM_ZB);

    const int tid  = threadIdx.x;
    const int wid  = tid >> 5;
    const int lane = tid & 31;
    const int mi   = wid & 3;
    const int ni   = wid >> 2;
    const int pbase = blockIdx.x * PPC;
    const int count = min(PPC, N_PART - pbase);

    for (int s = tid; s < 25 * HDIM; s += NTHREADS) W1s[s] = W1[s];
    for (int s = tid; s < 4 * HDIM; s += NTHREADS) W1s[25 * HDIM + s] = 0.0f;
    if (tid < HDIM) { b1s[tid] = b1[tid]; b2s[tid] = b2[tid]; }
    if (tid < DDIM) b3s[tid] = b3[tid];
    for (int i = tid; i < (HDIM * DDIM) / 4; i += NTHREADS)
        ((float4*)W3s)[i] = ((const float4*)W3)[i];
    for (int i = tid; i < (128 * LDK * 2) / 4; i += NTHREADS) {
        ((uint32_t*)(smem + SM_AHI))[i] = 0u;
        ((uint32_t*)(smem + SM_ALO))[i] = 0u;
    }
    for (int s = tid; s < HDIM * HDIM; s += NTHREADS) {
        int k = s >> 7, n = s & 127;
        float w = W2[s];
        uint32_t hb = bf16_hi_bits(w);
        float lo = w - __uint_as_float(hb);
        ((uint16_t*)(smem + SM_BHI))[n * LDK + k] = (uint16_t)(hb >> 16);
        ((uint16_t*)(smem + SM_BLO))[n * LDK + k] = (uint16_t)(bf16x2_rn(lo, 0.f) & 0xFFFFu);
    }

    const int p  = tid >> 1;
    const int dh = (tid & 1) * 8;
    const int pg = pbase + p;
    const int pgc = pg < N_PART ? pg : N_PART - 1;
    {
        float* row = sIn + p * LDIN;
#pragma unroll
        for (int j = 0; j < 8; j++)
            row[1 + dh + j] = (p < count) ? X0[(size_t)pg * DDIM + dh + j] : 0.0f;
        if ((tid & 1) == 0) {
            row[0] = 0.0f;
            sV[p] = (p < count) ? V0[pg] : 0.0f;
#pragma unroll
            for (int j = 0; j < PDIM; j++)
                row[17 + j] = (p < count) ? obs[(size_t)pg * PDIM + j] : 0.0f;
            row[25] = 0.0f; row[26] = 0.0f; row[27] = 0.0f;
        }
    }
    __syncthreads();

    const float dt   = (float)(1.0 / (double)M_STEPS);
    const float sqdt = sqrtf(dt);
    const int ty = tid >> 4, tx = tid & 15;
    const int qr = lane >> 2, qc = lane & 3;

    const uint32_t aoff = (uint32_t)(((lane & 7) + ((lane >> 3) & 1) * 8) * LDK
                                     + (lane >> 4) * 8) * 2u;
    const uint32_t boff = (uint32_t)(((lane & 7) + (lane >> 4) * 8) * LDK
                                     + ((lane >> 3) & 1) * 8) * 2u;
    const uint32_t aHiBase = sb + SM_AHI + aoff + (uint32_t)(32 * mi) * LDK * 2u;
    const uint32_t aLoBase = sb + SM_ALO + aoff + (uint32_t)(32 * mi) * LDK * 2u;
    const uint32_t bHiBase = sb + SM_BHI + boff + (uint32_t)(64 * ni) * LDK * 2u;
    const uint32_t bLoBase = sb + SM_BLO + boff + (uint32_t)(64 * ni) * LDK * 2u;

    float2 b2v[8];
#pragma unroll
    for (int j = 0; j < 8; j++)
        b2v[j] = *(const float2*)(b2s + 64 * ni + 8 * j + 2 * qc);
    const float4 b1A = *(const float4*)(b1s + 4 * tx);
    const float4 b1B = *(const float4*)(b1s + 64 + 4 * tx);
    const float4 b3a = *(const float4*)(b3s + dh);
    const float4 b3b = *(const float4*)(b3s + dh + 4);

    for (int m = 0; m < M_STEPS; m++) {
        // ---- layer 1 ----
        u64 c1[NROW][4];
#pragma unroll
        for (int i = 0; i < NROW; i++) { c1[i][0]=0; c1[i][1]=0; c1[i][2]=0; c1[i][3]=0; }
        mm_tile_v<7, LDIN, HDIM>(sIn + ty * LDIN, W1s + 4 * tx, c1);
#pragma unroll
        for (int i = 0; i < NROW; i++) {
            int row = ty + 16 * i;
            float2 v0 = unpack2(c1[i][0]), v1 = unpack2(c1[i][1]);
            float2 v2 = unpack2(c1[i][2]), v3 = unpack2(c1[i][3]);
            split_store4(smem, (uint32_t)(row * LDK + 4 * tx) * 2u,
                         fmaxf(v0.x + b1A.x, 0.f), fmaxf(v0.y + b1A.y, 0.f),
                         fmaxf(v1.x + b1A.z, 0.f), fmaxf(v1.y + b1A.w, 0.f));
            split_store4(smem, (uint32_t)(row * LDK + 64 + 4 * tx) * 2u,
                         fmaxf(v2.x + b1B.x, 0.f), fmaxf(v2.y + b1B.y, 0.f),
                         fmaxf(v3.x + b1B.z, 0.f), fmaxf(v3.y + b1B.w, 0.f));
        }
        __syncthreads();

        const float* np = noise + (((size_t)m * N_PART + pgc) * DDIM + dh);
        float4 e0 = *(const float4*)np;
        float4 e1 = *(const float4*)(np + 4);

        // ---- layer 2: HMMA bf16-split ----
        float acc[2][8][4];
#pragma unroll
        for (int a = 0; a < 2; a++)
#pragma unroll
            for (int j = 0; j < 8; j++) {
                acc[a][j][0]=0.f; acc[a][j][1]=0.f; acc[a][j][2]=0.f; acc[a][j][3]=0.f;
            }
#pragma unroll
        for (int k16 = 0; k16 < 8; k16++) {
            const uint32_t kb = (uint32_t)(k16 * 16) * 2u;
            uint32_t ah[2][4], al[2][4];
            ldsm4(ah[0], aHiBase + kb);
            ldsm4(ah[1], aHiBase + kb + (uint32_t)(16 * LDK) * 2u);
            ldsm4(al[0], aLoBase + kb);
            ldsm4(al[1], aLoBase + kb + (uint32_t)(16 * LDK) * 2u);
#pragma unroll
            for (int j2 = 0; j2 < 4; j2++) {
                uint32_t bh[4], bl[4];
                const uint32_t nb = (uint32_t)(16 * j2 * LDK) * 2u + kb;
                ldsm4(bh, bHiBase + nb);
                ldsm4(bl, bLoBase + nb);
#pragma unroll
                for (int a = 0; a < 2; a++) {
                    mma_bf16(acc[a][2 * j2],     ah[a], bh[0], bh[1]);
                    mma_bf16(acc[a][2 * j2],     ah[a], bl[0], bl[1]);
                    mma_bf16(acc[a][2 * j2],     al[a], bh[0], bh[1]);
                    mma_bf16(acc[a][2 * j2 + 1], ah[a], bh[2], bh[3]);
                    mma_bf16(acc[a][2 * j2 + 1], ah[a], bl[2], bl[3]);
                    mma_bf16(acc[a][2 * j2 + 1], al[a], bh[2], bh[3]);
                }
            }
        }

        // ---- fused epilogue + layer 3 ----
        u64 zr[4][8];
#pragma unroll
        for (int r = 0; r < 4; r++)
#pragma unroll
            for (int q = 0; q < 8; q++) zr[r][q] = 0ull;
#pragma unroll
        for (int j = 0; j < 8; j++) {
            const int col0 = 64 * ni + 8 * j + 2 * qc;
            u64 w0[8], w1[8];
#pragma unroll
            for (int q = 0; q < 4; q++) {
                ulonglong2 t0 = *(const ulonglong2*)(W3s + col0 * DDIM + 4 * q);
                w0[2 * q] = t0.x; w0[2 * q + 1] = t0.y;
                ulonglong2 t1 = *(const ulonglong2*)(W3s + (col0 + 1) * DDIM + 4 * q);
                w1[2 * q] = t1.x; w1[2 * q + 1] = t1.y;
            }
#pragma unroll
            for (int a = 0; a < 2; a++) {
                float h00 = fmaxf(acc[a][j][0] + b2v[j].x, 0.f);
                float h01 = fmaxf(acc[a][j][1] + b2v[j].y, 0.f);
                float h10 = fmaxf(acc[a][j][2] + b2v[j].x, 0.f);
                float h11 = fmaxf(acc[a][j][3] + b2v[j].y, 0.f);
                u64 p00 = pack2(h00, h00), p01 = pack2(h01, h01);
                u64 p10 = pack2(h10, h10), p11 = pack2(h11, h11);
#pragma unroll
                for (int q = 0; q < 8; q++) {
                    zr[2 * a][q]     = fma2(p00, w0[q], zr[2 * a][q]);
                    zr[2 * a][q]     = fma2(p01, w1[q], zr[2 * a][q]);
                    zr[2 * a + 1][q] = fma2(p10, w0[q], zr[2 * a + 1][q]);
                    zr[2 * a + 1][q] = fma2(p11, w1[q], zr[2 * a + 1][q]);
                }
            }
        }
        // quad reduction: float2-wise shuffle adds across qc = lane&3
#pragma unroll
        for (int r = 0; r < 4; r++)
#pragma unroll
            for (int q = 0; q < 8; q++) {
                float2 v = unpack2(zr[r][q]);
                v.x += __shfl_xor_sync(0xffffffffu, v.x, 1);
                v.y += __shfl_xor_sync(0xffffffffu, v.y, 1);
                v.x += __shfl_xor_sync(0xffffffffu, v.x, 2);
                v.y += __shfl_xor_sync(0xffffffffu, v.y, 2);
                zr[r][q] = pack2(v.x, v.y);
            }
        if (qc == 0) {
#pragma unroll
            for (int r = 0; r < 4; r++) {
                const int row = 32 * mi + 8 * r + qr;
                float* zp = zbuf + (size_t)(ni * 128 + row) * LDZ;
#pragma unroll
                for (int q = 0; q < 4; q++) {
                    float2 lo = unpack2(zr[r][2 * q]);
                    float2 hi = unpack2(zr[r][2 * q + 1]);
                    float4 o = { lo.x, lo.y, hi.x, hi.y };
                    *(float4*)(zp + 4 * q) = o;
                }
            }
        }
        __syncthreads();

        // ---- V / X update ----
        if (p < BLK_R) {
            float z8[8];
            const float* z0 = zbuf + (size_t)p * LDZ + dh;
            const float* z1 = zbuf + (size_t)(128 + p) * LDZ + dh;
            const float* f0 = (const float*)&b3a;
            const float* f1 = (const float*)&b3b;
#pragma unroll
            for (int j = 0; j < 4; j++) {
                z8[j]     = z0[j] + z1[j] + f0[j];
                z8[4 + j] = z0[4 + j] + z1[4 + j] + f1[j];
            }
            float eps[8] = { e0.x, e0.y, e0.z, e0.w, e1.x, e1.y, e1.z, e1.w };
            float zz = 0.0f, zw = 0.0f;
#pragma unroll
            for (int j = 0; j < 8; j++) {
                zz = fmaf(z8[j], z8[j], zz);
                zw = fmaf(z8[j], sqdt * eps[j], zw);
            }
            zz += __shfl_xor_sync(0xffffffffu, zz, 1);
            zw += __shfl_xor_sync(0xffffffffu, zw, 1);

            float* xr = sIn + p * LDIN + 1 + dh;
#pragma unroll
            for (int j = 0; j < 8; j++)
                xr[j] = fmaf(xr[j], 1.0f - dt, sqdt * eps[j]);
            if ((tid & 1) == 0) {
                sV[p] = sV[p] + dt * 0.5f * zz + zw;
                sIn[p * LDIN] = (float)(m + 1) * dt;
            }
        }
        __syncthreads();
    }

    if (p < count) {
        float* xo = out + (size_t)pg * DDIM + dh;
        const float* xr = sIn + p * LDIN + 1 + dh;
#pragma unroll
        for (int j = 0; j < 8; j++) xo[j] = xr[j];
        if ((tid & 1) == 0) out[(size_t)N_PART * DDIM + pg] = sV[p];
    }
}

extern "C" void kernel_launch(void* const* d_in, const int* in_sizes, int n_in,
                              void* d_out, int out_size) {
    const float* X0    = (const float*)d_in[0];
    const float* V0    = (const float*)d_in[1];
    const float* obs   = (const float*)d_in[2];
    const float* noise = (const float*)d_in[3];
    const float* W1    = (const float*)d_in[4];
    const float* b1    = (const float*)d_in[5];
    const float* W2    = (const float*)d_in[6];
    const float* b2    = (const float*)d_in[7];
    const float* W3    = (const float*)d_in[8];
    const float* b3    = (const float*)d_in[9];
    float* out = (float*)d_out;

    cudaFuncSetAttribute(sde_rollout_kernel,
                         cudaFuncAttributeMaxDynamicSharedMemorySize, SM_TOTAL);

    const int grid = (N_PART + PPC - 1) / PPC;   // 148
    sde_rollout_kernel<<<grid, NTHREADS, SM_TOTAL>>>(
        X0, V0, obs, noise, W1, b1, W2, b2, W3, b3, out);
}